// round 1
// baseline (speedup 1.0000x reference)
#include <cuda_runtime.h>
#include <cuda_bf16.h>

// out[i,j,k] = float(argmax_k encoding_logits[clamp(qv[i,j],-128,127)+128, :])
// (soft - stop_grad(soft) == 0 exactly in forward; gumbel_noise is never needed)

#define N_LEVELS 256
#define N_PIX (512 * 512)

__device__ float g_hard_table[N_LEVELS];

// Stage 1: per-row argmax of encoding_logits [256 x 256] -> float table.
// One block of 256 threads, each thread scans one row (first-max tie-break,
// matching jnp.argmax).
__global__ void argmax_rows_kernel(const float* __restrict__ logits) {
    int r = threadIdx.x;
    const float* row = logits + r * N_LEVELS;
    float best = row[0];
    int bi = 0;
#pragma unroll 8
    for (int k = 1; k < N_LEVELS; ++k) {
        float v = row[k];
        if (v > best) { best = v; bi = k; }
    }
    g_hard_table[r] = (float)bi;
}

// Stage 2: broadcast-write. 64 threads per pixel, one float4 store each.
// gid == global float4 index (perfectly coalesced, store-only 256 MiB).
__global__ void __launch_bounds__(256) broadcast_kernel(
    const int* __restrict__ qv, float4* __restrict__ out) {
    int gid = blockIdx.x * blockDim.x + threadIdx.x;   // [0, N_PIX*64)
    int p = gid >> 6;
    int q = __ldg(qv + p);
    q = min(max(q, -128), 127) + 128;
    float v = g_hard_table[q];
    out[gid] = make_float4(v, v, v, v);
}

extern "C" void kernel_launch(void* const* d_in, const int* in_sizes, int n_in,
                              void* d_out, int out_size) {
    const int* qv = (const int*)d_in[0];           // [512,512] int32
    const float* logits = (const float*)d_in[1];   // [256,256] f32
    // d_in[2] (gumbel_noise) is mathematically unused.
    float4* out = (float4*)d_out;

    argmax_rows_kernel<<<1, N_LEVELS>>>(logits);

    int total_f4 = N_PIX * (N_LEVELS / 4);         // 16,777,216 threads
    broadcast_kernel<<<total_f4 / 256, 256>>>(qv, out);
}

// round 3
// speedup vs baseline: 2.2891x; 2.2891x over previous
#include <cuda_runtime.h>
#include <cuda_bf16.h>

// out[i,j,:] = float(argmax(encoding_logits[clamp(qv[i,j],-128,127)+128, :]))
// (soft_codes - stop_gradient(soft_codes) == 0 exactly; gumbel_noise unused)

#define N_LEVELS 256
#define N_PIX (512 * 512)

__device__ float g_hard_table[N_LEVELS];

// Stage 1: one WARP per row (needs 256 warps total!). Lane l scans columns
// l, l+32, ..., l+224 (coalesced), then shuffle-reduce with first-index
// tiebreak (matching jnp.argmax).
__global__ void argmax_rows_kernel(const float* __restrict__ logits) {
    int warp = (blockIdx.x * blockDim.x + threadIdx.x) >> 5;   // row 0..255
    int lane = threadIdx.x & 31;
    const float* row = logits + warp * N_LEVELS;

    float best = -__FLT_MAX__;
    int bi = N_LEVELS;
#pragma unroll
    for (int j = 0; j < N_LEVELS / 32; ++j) {
        int k = lane + j * 32;
        float v = row[k];
        if (v > best || (v == best && k < bi)) { best = v; bi = k; }
    }
#pragma unroll
    for (int off = 16; off > 0; off >>= 1) {
        float ov = __shfl_down_sync(0xffffffffu, best, off);
        int oi = __shfl_down_sync(0xffffffffu, bi, off);
        if (ov > best || (ov == best && oi < bi)) { best = ov; bi = oi; }
    }
    if (lane == 0) g_hard_table[warp] = (float)bi;
}

// Stage 2: streaming broadcast-write. Each block owns a contiguous 64 KB
// (1024 float4); each thread issues 4 fully-coalesced evict-first STG.128.
__global__ void __launch_bounds__(256) broadcast_kernel(
    const int* __restrict__ qv, float4* __restrict__ out) {
    long long base = (long long)blockIdx.x * 1024 + threadIdx.x;
#pragma unroll
    for (int j = 0; j < 4; ++j) {
        long long gid = base + j * 256;        // float4 index
        int p = (int)(gid >> 6);               // pixel index
        int q = __ldg(qv + p);
        q = min(max(q, -128), 127) + 128;
        float v = g_hard_table[q];
        __stcs(out + gid, make_float4(v, v, v, v));
    }
}

extern "C" void kernel_launch(void* const* d_in, const int* in_sizes, int n_in,
                              void* d_out, int out_size) {
    const int* qv = (const int*)d_in[0];           // [512,512] int32
    const float* logits = (const float*)d_in[1];   // [256,256] f32
    // d_in[2] (gumbel_noise) is mathematically unused.
    float4* out = (float4*)d_out;

    // 256 warps = 32 blocks x 8 warps  (R2 bug: was 8 blocks -> 64 warps)
    argmax_rows_kernel<<<32, 256>>>(logits);

    int total_f4 = N_PIX * (N_LEVELS / 4);         // 16,777,216
    broadcast_kernel<<<total_f4 / 1024, 256>>>(qv, out);   // 16384 blocks
}

// round 4
// speedup vs baseline: 2.3032x; 1.0062x over previous
#include <cuda_runtime.h>
#include <cuda_bf16.h>

// out[i,j,:] = float(argmax(encoding_logits[clamp(qv[i,j],-128,127)+128, :]))
// (soft_codes - stop_gradient(soft_codes) == 0 exactly; gumbel_noise unused)

#define N_LEVELS 256
#define N_PIX (512 * 512)

__device__ float g_hard_table[N_LEVELS];

// Stage 1: one WARP per row (256 warps = 32 blocks x 8 warps). Lane l scans
// columns l, l+32, ..., l+224 (coalesced), then shuffle-reduce with
// first-index tiebreak (matching jnp.argmax).
__global__ void argmax_rows_kernel(const float* __restrict__ logits) {
    int warp = (blockIdx.x * blockDim.x + threadIdx.x) >> 5;   // row 0..255
    int lane = threadIdx.x & 31;
    const float* row = logits + warp * N_LEVELS;

    float best = -__FLT_MAX__;
    int bi = N_LEVELS;
#pragma unroll
    for (int j = 0; j < N_LEVELS / 32; ++j) {
        int k = lane + j * 32;
        float v = row[k];
        if (v > best || (v == best && k < bi)) { best = v; bi = k; }
    }
#pragma unroll
    for (int off = 16; off > 0; off >>= 1) {
        float ov = __shfl_down_sync(0xffffffffu, best, off);
        int oi = __shfl_down_sync(0xffffffffu, bi, off);
        if (ov > best || (ov == best && oi < bi)) { best = ov; bi = oi; }
    }
    if (lane == 0) g_hard_table[warp] = (float)bi;
}

// Stage 2: resolve pixel value ONCE per thread, then stream 8 independent
// evict-first STG.128. Block covers 32 pixels (128 KB contiguous):
//   8 threads per pixel; thread t -> pixel (t>>3), f4 offsets (t&7)+8j.
// Per-warp store = 4 x 128B sector-aligned segments (fully coalesced).
__global__ void __launch_bounds__(256) broadcast_kernel(
    const int* __restrict__ qv, float4* __restrict__ out) {
    int t = threadIdx.x;
    int pix = blockIdx.x * 32 + (t >> 3);         // pixel index
    int q = __ldg(qv + pix);
    q = min(max(q, -128), 127) + 128;
    float v = g_hard_table[q];
    float4 v4 = make_float4(v, v, v, v);

    float4* p = out + (long long)pix * 64 + (t & 7);
#pragma unroll
    for (int j = 0; j < 8; ++j)
        __stcs(p + j * 8, v4);
}

extern "C" void kernel_launch(void* const* d_in, const int* in_sizes, int n_in,
                              void* d_out, int out_size) {
    const int* qv = (const int*)d_in[0];           // [512,512] int32
    const float* logits = (const float*)d_in[1];   // [256,256] f32
    // d_in[2] (gumbel_noise) is mathematically unused.
    float4* out = (float4*)d_out;

    argmax_rows_kernel<<<32, 256>>>(logits);       // 256 warps, 1 per row

    broadcast_kernel<<<N_PIX / 32, 256>>>(qv, out); // 8192 blocks
}